// round 3
// baseline (speedup 1.0000x reference)
#include <cuda_runtime.h>
#include <cuda_bf16.h>
#include <cstdint>

// Problem dims
#define Vv 32000
#define Ee 512
#define Hh 512
#define Bb 16
#define Ss 128
#define H4 (4*Hh)       // 2048
#define MROWS (Ss*Bb)   // 2048

// -------- device scratch (no allocation allowed) --------
__device__ float g_x0[MROWS * Ee];        // [s*B+b][E]      4MB
__device__ float g_x1[MROWS * 2 * Hh];    // layer0 output   8MB
__device__ float g_x2[MROWS * 2 * Hh];    // layer1 output   8MB
__device__ float g_xg_f[MROWS * H4];      // 16MB
__device__ float g_xg_b[MROWS * H4];      // 16MB
__device__ float g_h[2 * 2 * Bb * Hh];    // [parity][dir][b*H]
__device__ float g_c[2 * Bb * Hh];        // [dir][b*H]

// -------- embedding: x0[s][b][e] = embed_w[input[b][s]][e] --------
__global__ void embed_kernel(const int* __restrict__ idx,
                             const float* __restrict__ ew) {
    int sb = blockIdx.x;           // 0..2047
    int s = sb >> 4, b = sb & 15;
    int token = idx[b * Ss + s];
    const float4* src = (const float4*)(ew + (size_t)token * Ee);
    float4* dst = (float4*)(g_x0 + ((size_t)s * Bb + b) * Ee);
    dst[threadIdx.x] = src[threadIdx.x];   // 128 threads x float4 = 512
}

// -------- zero h(parity 0) and c --------
__global__ void zero_state() {
    int i = blockIdx.x * 256 + threadIdx.x;
    if (i < 2 * Bb * Hh) {
        g_h[i] = 0.f;   // parity-0 slab for both dirs
        g_c[i] = 0.f;
    }
}

// -------- generic NT SGEMM with two-bias epilogue: C[m][n] = A[m,:].B[n,:] + b1[n]+b2[n]
// BM=BN=128, BK=8, TM=TN=8, 256 threads
__global__ __launch_bounds__(256)
void sgemm_xg(const float* __restrict__ A, const float* __restrict__ Bw,
              const float* __restrict__ b1, const float* __restrict__ b2,
              float* __restrict__ C, int M, int N, int K) {
    __shared__ float As[8][128];
    __shared__ float Bs[8][128];
    int tid = threadIdx.x;
    int tx = tid & 15, ty = tid >> 4;
    int bm = blockIdx.y * 128, bn = blockIdx.x * 128;
    float acc[8][8];
    #pragma unroll
    for (int i = 0; i < 8; i++)
        #pragma unroll
        for (int j = 0; j < 8; j++) acc[i][j] = 0.f;

    int lrow = tid >> 1, lcol = (tid & 1) * 4;
    const float* Ap = A + (size_t)(bm + lrow) * K + lcol;
    const float* Bp = Bw + (size_t)(bn + lrow) * K + lcol;

    for (int k0 = 0; k0 < K; k0 += 8) {
        float4 av = *(const float4*)(Ap + k0);
        float4 bv = *(const float4*)(Bp + k0);
        As[lcol + 0][lrow] = av.x; As[lcol + 1][lrow] = av.y;
        As[lcol + 2][lrow] = av.z; As[lcol + 3][lrow] = av.w;
        Bs[lcol + 0][lrow] = bv.x; Bs[lcol + 1][lrow] = bv.y;
        Bs[lcol + 2][lrow] = bv.z; Bs[lcol + 3][lrow] = bv.w;
        __syncthreads();
        #pragma unroll
        for (int kk = 0; kk < 8; kk++) {
            float a[8], br[8];
            #pragma unroll
            for (int i = 0; i < 8; i++) a[i] = As[kk][ty * 8 + i];
            #pragma unroll
            for (int j = 0; j < 8; j++) br[j] = Bs[kk][tx * 8 + j];
            #pragma unroll
            for (int i = 0; i < 8; i++)
                #pragma unroll
                for (int j = 0; j < 8; j++) acc[i][j] += a[i] * br[j];
        }
        __syncthreads();
    }
    #pragma unroll
    for (int i = 0; i < 8; i++) {
        int m = bm + ty * 8 + i;
        #pragma unroll
        for (int j = 0; j < 8; j++) {
            int n = bn + tx * 8 + j;
            C[(size_t)m * N + n] = acc[i][j] + b1[n] + b2[n];
        }
    }
}

// -------- final GEMM with [B,V,S] scatter epilogue: out[b][v][s] --------
__global__ __launch_bounds__(256)
void sgemm_out(const float* __restrict__ A, const float* __restrict__ Bw,
               const float* __restrict__ bias, float* __restrict__ C,
               int M, int N, int K) {
    __shared__ float As[8][128];
    __shared__ float Bs[8][128];
    int tid = threadIdx.x;
    int tx = tid & 15, ty = tid >> 4;
    int bm = blockIdx.y * 128, bn = blockIdx.x * 128;
    float acc[8][8];
    #pragma unroll
    for (int i = 0; i < 8; i++)
        #pragma unroll
        for (int j = 0; j < 8; j++) acc[i][j] = 0.f;

    int lrow = tid >> 1, lcol = (tid & 1) * 4;
    const float* Ap = A + (size_t)(bm + lrow) * K + lcol;
    const float* Bp = Bw + (size_t)(bn + lrow) * K + lcol;

    for (int k0 = 0; k0 < K; k0 += 8) {
        float4 av = *(const float4*)(Ap + k0);
        float4 bv = *(const float4*)(Bp + k0);
        As[lcol + 0][lrow] = av.x; As[lcol + 1][lrow] = av.y;
        As[lcol + 2][lrow] = av.z; As[lcol + 3][lrow] = av.w;
        Bs[lcol + 0][lrow] = bv.x; Bs[lcol + 1][lrow] = bv.y;
        Bs[lcol + 2][lrow] = bv.z; Bs[lcol + 3][lrow] = bv.w;
        __syncthreads();
        #pragma unroll
        for (int kk = 0; kk < 8; kk++) {
            float a[8], br[8];
            #pragma unroll
            for (int i = 0; i < 8; i++) a[i] = As[kk][ty * 8 + i];
            #pragma unroll
            for (int j = 0; j < 8; j++) br[j] = Bs[kk][tx * 8 + j];
            #pragma unroll
            for (int i = 0; i < 8; i++)
                #pragma unroll
                for (int j = 0; j < 8; j++) acc[i][j] += a[i] * br[j];
        }
        __syncthreads();
    }
    #pragma unroll
    for (int i = 0; i < 8; i++) {
        int m = bm + ty * 8 + i;
        int s = m >> 4, b = m & 15;      // m = s*16 + b
        #pragma unroll
        for (int j = 0; j < 8; j++) {
            int v = bn + tx * 8 + j;
            C[((size_t)b * Vv + v) * Ss + s] = acc[i][j] + bias[v];
        }
    }
}

// -------- fused LSTM step: both directions, one time step --------
// grid = 128 blocks (dir = bid&1, jblk = bid>>1), 128 threads (b = tid&15, jl = tid>>4)
__global__ __launch_bounds__(128)
void lstm_step(const float* __restrict__ xg_f, const float* __restrict__ xg_b,
               const float* __restrict__ Whh_f, const float* __restrict__ Whh_b,
               float* __restrict__ xnext, int t) {
    __shared__ float hs[Hh * 17];   // hs[k*17 + b], padded, conflict-free both ways

    int dir = blockIdx.x & 1;
    int jblk = blockIdx.x >> 1;         // 0..63
    int tid = threadIdx.x;
    int b = tid & 15, jl = tid >> 4;    // jl 0..7
    int j = jblk * 8 + jl;

    const float* Whh = dir ? Whh_b : Whh_f;
    const float* xg = dir ? xg_b : xg_f;
    int tt = dir ? (Ss - 1 - t) : t;

    const float* hread = g_h + (size_t)(t & 1) * (2 * Bb * Hh) + (size_t)dir * (Bb * Hh);
    float* hwrite = g_h + (size_t)((t + 1) & 1) * (2 * Bb * Hh) + (size_t)dir * (Bb * Hh);
    float* cstate = g_c + (size_t)dir * (Bb * Hh);

    // stage h (read buffer) into smem, transposed to [k][b]
    for (int idx = tid; idx < Bb * Hh; idx += 128) {
        int bb = idx >> 9;      // /512
        int kk = idx & 511;
        hs[kk * 17 + bb] = hread[idx];
    }
    __syncthreads();

    const float4* wi = (const float4*)(Whh + (size_t)(0 * Hh + j) * Hh);
    const float4* wf = (const float4*)(Whh + (size_t)(1 * Hh + j) * Hh);
    const float4* wg = (const float4*)(Whh + (size_t)(2 * Hh + j) * Hh);
    const float4* wo = (const float4*)(Whh + (size_t)(3 * Hh + j) * Hh);

    float ai = 0.f, af = 0.f, ag = 0.f, ao = 0.f;
    #pragma unroll 4
    for (int k4 = 0; k4 < Hh / 4; k4++) {
        float4 vi = __ldg(wi + k4);
        float4 vf = __ldg(wf + k4);
        float4 vg = __ldg(wg + k4);
        float4 vo = __ldg(wo + k4);
        int k = k4 * 4;
        float h0 = hs[(k + 0) * 17 + b];
        float h1 = hs[(k + 1) * 17 + b];
        float h2 = hs[(k + 2) * 17 + b];
        float h3 = hs[(k + 3) * 17 + b];
        ai += vi.x * h0 + vi.y * h1 + vi.z * h2 + vi.w * h3;
        af += vf.x * h0 + vf.y * h1 + vf.z * h2 + vf.w * h3;
        ag += vg.x * h0 + vg.y * h1 + vg.z * h2 + vg.w * h3;
        ao += vo.x * h0 + vo.y * h1 + vo.z * h2 + vo.w * h3;
    }

    size_t base = ((size_t)tt * Bb + b) * (size_t)H4;
    ai += xg[base + 0 * Hh + j];
    af += xg[base + 1 * Hh + j];
    ag += xg[base + 2 * Hh + j];
    ao += xg[base + 3 * Hh + j];

    float ii = 1.f / (1.f + __expf(-ai));
    float ff = 1.f / (1.f + __expf(-af));
    float gg = tanhf(ag);
    float oo = 1.f / (1.f + __expf(-ao));

    int sidx = b * Hh + j;
    float c = ff * cstate[sidx] + ii * gg;
    float h = oo * tanhf(c);
    cstate[sidx] = c;
    hwrite[sidx] = h;
    xnext[((size_t)tt * Bb + b) * (size_t)(2 * Hh) + (size_t)dir * Hh + j] = h;
}

// ---------------- host launcher ----------------
extern "C" void kernel_launch(void* const* d_in, const int* in_sizes, int n_in,
                              void* d_out, int out_size) {
    const int* input = (const int*)d_in[0];
    const float* embed_w = (const float*)d_in[1];
    // per layer/dir param groups: Wih, Whh, bih, bhh
    const float* Wih[2][2]; const float* Whh[2][2];
    const float* bih[2][2]; const float* bhh[2][2];
    int p = 2;
    for (int l = 0; l < 2; l++) {
        for (int d = 0; d < 2; d++) {  // d=0 fwd, d=1 bwd
            Wih[l][d] = (const float*)d_in[p++];
            Whh[l][d] = (const float*)d_in[p++];
            bih[l][d] = (const float*)d_in[p++];
            bhh[l][d] = (const float*)d_in[p++];
        }
    }
    const float* lin_w = (const float*)d_in[18];
    const float* lin_b = (const float*)d_in[19];
    float* out = (float*)d_out;

    float *x0p, *x1p, *x2p, *xgf, *xgb;
    cudaGetSymbolAddress((void**)&x0p, g_x0);
    cudaGetSymbolAddress((void**)&x1p, g_x1);
    cudaGetSymbolAddress((void**)&x2p, g_x2);
    cudaGetSymbolAddress((void**)&xgf, g_xg_f);
    cudaGetSymbolAddress((void**)&xgb, g_xg_b);

    // 1) embedding
    embed_kernel<<<MROWS, 128>>>(input, embed_w);

    const float* xin = x0p;
    float* xouts[2] = {x1p, x2p};
    int kdims[2] = {Ee, 2 * Hh};

    for (int l = 0; l < 2; l++) {
        int K = kdims[l];
        dim3 ggrid(H4 / 128, MROWS / 128);
        sgemm_xg<<<ggrid, 256>>>(xin, Wih[l][0], bih[l][0], bhh[l][0], xgf,
                                 MROWS, H4, K);
        sgemm_xg<<<ggrid, 256>>>(xin, Wih[l][1], bih[l][1], bhh[l][1], xgb,
                                 MROWS, H4, K);
        zero_state<<<64, 256>>>();
        for (int t = 0; t < Ss; t++) {
            lstm_step<<<128, 128>>>(xgf, xgb, Whh[l][0], Whh[l][1], xouts[l], t);
        }
        xin = xouts[l];
    }

    // 3) vocab projection with [B,V,S] scatter
    dim3 ogrid(Vv / 128, MROWS / 128);
    sgemm_out<<<ogrid, 256>>>(x2p, lin_w, lin_b, out, MROWS, Vv, 2 * Hh);
}

// round 4
// speedup vs baseline: 1.0165x; 1.0165x over previous
#include <cuda_runtime.h>
#include <cuda_bf16.h>
#include <cstdint>

// Problem dims
#define Vv 32000
#define Ee 512
#define Hh 512
#define Bb 16
#define Ss 128
#define H4 (4*Hh)       // 2048
#define MROWS (Ss*Bb)   // 2048

// -------- device scratch (no allocation allowed) --------
__device__ float g_x0[MROWS * Ee];        // [s*B+b][E]      4MB
__device__ float g_x1[MROWS * 2 * Hh];    // layer0 output   8MB
__device__ float g_x2[MROWS * 2 * Hh];    // layer1 output   8MB
__device__ float g_xg_f[MROWS * H4];      // 16MB
__device__ float g_xg_b[MROWS * H4];      // 16MB
__device__ float g_h[2 * 2 * Bb * Hh];    // [parity][dir][b*H]
__device__ float g_c[2 * Bb * Hh];        // [dir][b*H]

// -------- embedding: x0[s][b][e] = embed_w[input[b][s]][e] --------
__global__ void embed_kernel(const int* __restrict__ idx,
                             const float* __restrict__ ew) {
    int sb = blockIdx.x;           // 0..2047
    int s = sb >> 4, b = sb & 15;
    int token = idx[b * Ss + s];
    const float4* src = (const float4*)(ew + (size_t)token * Ee);
    float4* dst = (float4*)(g_x0 + ((size_t)s * Bb + b) * Ee);
    dst[threadIdx.x] = src[threadIdx.x];   // 128 threads x float4 = 512
}

// -------- zero h(parity 0) and c --------
__global__ void zero_state() {
    int i = blockIdx.x * 256 + threadIdx.x;
    if (i < 2 * Bb * Hh) {
        g_h[i] = 0.f;   // parity-0 slab for both dirs
        g_c[i] = 0.f;
    }
}

// ============================================================
// TF32 tensor-core GEMM  (NT: A[M][K] row-major, B[N][K] -> C=A.B^T)
// BM=BN=128, BK=32, 256 threads = 8 warps, warp tile 64x32.
// mma.sync.aligned.m16n8k8.row.col.f32.tf32.tf32.f32
// 2-stage cp.async pipeline, dynamic smem.
// mode 0: C[m*N+n] = acc + b1[n] + b2[n]
// mode 1: out[((m&15)*V + n)*S + (m>>4)] = acc + b1[n]   (vocab scatter)
// ============================================================
#define BKP 36                     // BK(32) + 4 pad (keeps 16B align, kills conflicts)
#define TILE_F (128 * BKP)         // floats per tile per stage = 4608
#define SMEM_FLOATS (4 * TILE_F)   // A(2 stages) + B(2 stages) = 18432 floats = 72KB

__device__ __forceinline__ uint32_t f2tf32(float f) {
    uint32_t r;
    asm("cvt.rna.tf32.f32 %0, %1;" : "=r"(r) : "f"(f));
    return r;
}

__device__ __forceinline__ void mma_tf32(float* c, const uint32_t* a, const uint32_t* b) {
    asm volatile(
        "mma.sync.aligned.m16n8k8.row.col.f32.tf32.tf32.f32 "
        "{%0,%1,%2,%3}, {%4,%5,%6,%7}, {%8,%9}, {%0,%1,%2,%3};"
        : "+f"(c[0]), "+f"(c[1]), "+f"(c[2]), "+f"(c[3])
        : "r"(a[0]), "r"(a[1]), "r"(a[2]), "r"(a[3]), "r"(b[0]), "r"(b[1]));
}

__device__ __forceinline__ void cp_async16(uint32_t smem_addr, const void* gptr) {
    asm volatile("cp.async.cg.shared.global [%0], [%1], 16;"
                 :: "r"(smem_addr), "l"(gptr));
}

__global__ __launch_bounds__(256)
void tf32_gemm(const float* __restrict__ A, const float* __restrict__ Bw,
               const float* __restrict__ b1, const float* __restrict__ b2,
               float* __restrict__ C, int M, int N, int K, int mode) {
    extern __shared__ float smem[];   // [A stage0][A stage1][B stage0][B stage1]
    const int tid = threadIdx.x;
    const int lane = tid & 31, wid = tid >> 5;
    const int gid = lane >> 2, tig = lane & 3;
    const int wm = (wid & 1) * 64;        // warp m offset within block
    const int wn = (wid >> 1) * 32;       // warp n offset within block
    const int bm = blockIdx.x * 128, bn = blockIdx.y * 128;

    uint32_t s_base = (uint32_t)__cvta_generic_to_shared(smem);

    float acc[4][4][4];
    #pragma unroll
    for (int i = 0; i < 4; i++)
        #pragma unroll
        for (int j = 0; j < 4; j++)
            #pragma unroll
            for (int e = 0; e < 4; e++) acc[i][j][e] = 0.f;

    const int NT = K >> 5;   // K / 32

    // per-thread gmem/smem copy assignment: 4 float4 for A, 4 for B
    // f = tid + i*256 : row = f>>3 (0..127), c4 = f&7 (float4 col)
    auto load_tiles = [&](int st, int kof) {
        #pragma unroll
        for (int i = 0; i < 4; i++) {
            int f = tid + i * 256;
            int row = f >> 3, c4 = f & 7;
            const float* srcA = A + (size_t)(bm + row) * K + kof + c4 * 4;
            uint32_t dstA = s_base + (uint32_t)(((st * 128 + row) * BKP + c4 * 4) * 4);
            cp_async16(dstA, srcA);
            const float* srcB = Bw + (size_t)(bn + row) * K + kof + c4 * 4;
            uint32_t dstB = s_base + (uint32_t)((2 * TILE_F + (st * 128 + row) * BKP + c4 * 4) * 4);
            cp_async16(dstB, srcB);
        }
        asm volatile("cp.async.commit_group;");
    };

    load_tiles(0, 0);

    for (int kt = 0; kt < NT; kt++) {
        if (kt + 1 < NT) {
            load_tiles((kt + 1) & 1, (kt + 1) * 32);
            asm volatile("cp.async.wait_group 1;");
        } else {
            asm volatile("cp.async.wait_group 0;");
        }
        __syncthreads();

        const float* as = smem + (kt & 1) * TILE_F;
        const float* bs = smem + 2 * TILE_F + (kt & 1) * TILE_F;

        #pragma unroll
        for (int ks = 0; ks < 4; ks++) {
            const int k0 = ks * 8;
            uint32_t af[4][4], bf[4][2];
            #pragma unroll
            for (int mt = 0; mt < 4; mt++) {
                int r = wm + mt * 16 + gid;
                af[mt][0] = f2tf32(as[r * BKP + k0 + tig]);
                af[mt][1] = f2tf32(as[(r + 8) * BKP + k0 + tig]);
                af[mt][2] = f2tf32(as[r * BKP + k0 + tig + 4]);
                af[mt][3] = f2tf32(as[(r + 8) * BKP + k0 + tig + 4]);
            }
            #pragma unroll
            for (int nt = 0; nt < 4; nt++) {
                int rn = wn + nt * 8 + gid;
                bf[nt][0] = f2tf32(bs[rn * BKP + k0 + tig]);
                bf[nt][1] = f2tf32(bs[rn * BKP + k0 + tig + 4]);
            }
            #pragma unroll
            for (int mt = 0; mt < 4; mt++)
                #pragma unroll
                for (int nt = 0; nt < 4; nt++)
                    mma_tf32(acc[mt][nt], af[mt], bf[nt]);
        }
        __syncthreads();
    }

    // -------- epilogue --------
    #pragma unroll
    for (int mt = 0; mt < 4; mt++) {
        int m0 = bm + wm + mt * 16 + gid;   // rows m0 and m0+8
        #pragma unroll
        for (int nt = 0; nt < 4; nt++) {
            int n = bn + wn + nt * 8 + tig * 2;   // cols n, n+1
            float* a = acc[mt][nt];
            if (mode == 0) {
                float bb0 = b1[n] + b2[n];
                float bb1 = b1[n + 1] + b2[n + 1];
                *(float2*)(C + (size_t)m0 * N + n) = make_float2(a[0] + bb0, a[1] + bb1);
                *(float2*)(C + (size_t)(m0 + 8) * N + n) = make_float2(a[2] + bb0, a[3] + bb1);
            } else {
                float bb0 = b1[n], bb1 = b1[n + 1];
                int s0 = m0 >> 4, b0 = m0 & 15;
                int s1 = (m0 + 8) >> 4, b1i = (m0 + 8) & 15;
                C[((size_t)b0 * Vv + n) * Ss + s0]       = a[0] + bb0;
                C[((size_t)b0 * Vv + n + 1) * Ss + s0]   = a[1] + bb1;
                C[((size_t)b1i * Vv + n) * Ss + s1]      = a[2] + bb0;
                C[((size_t)b1i * Vv + n + 1) * Ss + s1]  = a[3] + bb1;
            }
        }
    }
}

// -------- fused LSTM step: both directions, one time step --------
__global__ __launch_bounds__(128)
void lstm_step(const float* __restrict__ xg_f, const float* __restrict__ xg_b,
               const float* __restrict__ Whh_f, const float* __restrict__ Whh_b,
               float* __restrict__ xnext, int t) {
    __shared__ float hs[Hh * 17];   // hs[k*17 + b], padded, conflict-free both ways

    int dir = blockIdx.x & 1;
    int jblk = blockIdx.x >> 1;         // 0..63
    int tid = threadIdx.x;
    int b = tid & 15, jl = tid >> 4;    // jl 0..7
    int j = jblk * 8 + jl;

    const float* Whh = dir ? Whh_b : Whh_f;
    const float* xg = dir ? xg_b : xg_f;
    int tt = dir ? (Ss - 1 - t) : t;

    const float* hread = g_h + (size_t)(t & 1) * (2 * Bb * Hh) + (size_t)dir * (Bb * Hh);
    float* hwrite = g_h + (size_t)((t + 1) & 1) * (2 * Bb * Hh) + (size_t)dir * (Bb * Hh);
    float* cstate = g_c + (size_t)dir * (Bb * Hh);

    for (int idx = tid; idx < Bb * Hh; idx += 128) {
        int bb = idx >> 9;
        int kk = idx & 511;
        hs[kk * 17 + bb] = hread[idx];
    }
    __syncthreads();

    const float4* wi = (const float4*)(Whh + (size_t)(0 * Hh + j) * Hh);
    const float4* wf = (const float4*)(Whh + (size_t)(1 * Hh + j) * Hh);
    const float4* wg = (const float4*)(Whh + (size_t)(2 * Hh + j) * Hh);
    const float4* wo = (const float4*)(Whh + (size_t)(3 * Hh + j) * Hh);

    float ai = 0.f, af = 0.f, ag = 0.f, ao = 0.f;
    #pragma unroll 4
    for (int k4 = 0; k4 < Hh / 4; k4++) {
        float4 vi = __ldg(wi + k4);
        float4 vf = __ldg(wf + k4);
        float4 vg = __ldg(wg + k4);
        float4 vo = __ldg(wo + k4);
        int k = k4 * 4;
        float h0 = hs[(k + 0) * 17 + b];
        float h1 = hs[(k + 1) * 17 + b];
        float h2 = hs[(k + 2) * 17 + b];
        float h3 = hs[(k + 3) * 17 + b];
        ai += vi.x * h0 + vi.y * h1 + vi.z * h2 + vi.w * h3;
        af += vf.x * h0 + vf.y * h1 + vf.z * h2 + vf.w * h3;
        ag += vg.x * h0 + vg.y * h1 + vg.z * h2 + vg.w * h3;
        ao += vo.x * h0 + vo.y * h1 + vo.z * h2 + vo.w * h3;
    }

    size_t base = ((size_t)tt * Bb + b) * (size_t)H4;
    ai += xg[base + 0 * Hh + j];
    af += xg[base + 1 * Hh + j];
    ag += xg[base + 2 * Hh + j];
    ao += xg[base + 3 * Hh + j];

    float ii = 1.f / (1.f + __expf(-ai));
    float ff = 1.f / (1.f + __expf(-af));
    float gg = tanhf(ag);
    float oo = 1.f / (1.f + __expf(-ao));

    int sidx = b * Hh + j;
    float c = ff * cstate[sidx] + ii * gg;
    float h = oo * tanhf(c);
    cstate[sidx] = c;
    hwrite[sidx] = h;
    xnext[((size_t)tt * Bb + b) * (size_t)(2 * Hh) + (size_t)dir * Hh + j] = h;
}

// ---------------- host launcher ----------------
extern "C" void kernel_launch(void* const* d_in, const int* in_sizes, int n_in,
                              void* d_out, int out_size) {
    const int* input = (const int*)d_in[0];
    const float* embed_w = (const float*)d_in[1];
    const float* Wih[2][2]; const float* Whh[2][2];
    const float* bih[2][2]; const float* bhh[2][2];
    int p = 2;
    for (int l = 0; l < 2; l++) {
        for (int d = 0; d < 2; d++) {  // d=0 fwd, d=1 bwd
            Wih[l][d] = (const float*)d_in[p++];
            Whh[l][d] = (const float*)d_in[p++];
            bih[l][d] = (const float*)d_in[p++];
            bhh[l][d] = (const float*)d_in[p++];
        }
    }
    const float* lin_w = (const float*)d_in[18];
    const float* lin_b = (const float*)d_in[19];
    float* out = (float*)d_out;

    float *x0p, *x1p, *x2p, *xgf, *xgb;
    cudaGetSymbolAddress((void**)&x0p, g_x0);
    cudaGetSymbolAddress((void**)&x1p, g_x1);
    cudaGetSymbolAddress((void**)&x2p, g_x2);
    cudaGetSymbolAddress((void**)&xgf, g_xg_f);
    cudaGetSymbolAddress((void**)&xgb, g_xg_b);

    static int smem_set = 0;
    if (!smem_set) {
        cudaFuncSetAttribute(tf32_gemm, cudaFuncAttributeMaxDynamicSharedMemorySize,
                             SMEM_FLOATS * 4);
        smem_set = 1;
    }
    const size_t smem_bytes = SMEM_FLOATS * 4;

    // 1) embedding
    embed_kernel<<<MROWS, 128>>>(input, embed_w);

    const float* xin = x0p;
    float* xouts[2] = {x1p, x2p};
    int kdims[2] = {Ee, 2 * Hh};

    for (int l = 0; l < 2; l++) {
        int K = kdims[l];
        dim3 ggrid(MROWS / 128, H4 / 128);   // x = m-tiles, y = n-tiles
        tf32_gemm<<<ggrid, 256, smem_bytes>>>(xin, Wih[l][0], bih[l][0], bhh[l][0],
                                              xgf, MROWS, H4, K, 0);
        tf32_gemm<<<ggrid, 256, smem_bytes>>>(xin, Wih[l][1], bih[l][1], bhh[l][1],
                                              xgb, MROWS, H4, K, 0);
        zero_state<<<64, 256>>>();
        for (int t = 0; t < Ss; t++) {
            lstm_step<<<128, 128>>>(xgf, xgb, Whh[l][0], Whh[l][1], xouts[l], t);
        }
        xin = xouts[l];
    }

    // 3) vocab projection with [B,V,S] scatter
    // x = m-tiles (16) fastest -> co-resident CTAs share lin_w tiles via L2
    dim3 ogrid(MROWS / 128, Vv / 128);
    tf32_gemm<<<ogrid, 256, smem_bytes>>>(x2p, lin_w, lin_b, nullptr,
                                          out, MROWS, Vv, 2 * Hh, 1);
}

// round 5
// speedup vs baseline: 1.4607x; 1.4370x over previous
#include <cuda_runtime.h>
#include <cuda_bf16.h>
#include <cstdint>

// Problem dims
#define Vv 32000
#define Ee 512
#define Hh 512
#define Bb 16
#define Ss 128
#define H4 (4*Hh)       // 2048
#define MROWS (Ss*Bb)   // 2048

// -------- device scratch (no allocation allowed) --------
__device__ float g_x0[MROWS * Ee];        // [s*B+b][E]      4MB
__device__ float g_x1[MROWS * 2 * Hh];    // layer0 output   8MB
__device__ float g_x2[MROWS * 2 * Hh];    // layer1 output   8MB
__device__ float g_xg_f[MROWS * H4];      // 16MB
__device__ float g_xg_b[MROWS * H4];      // 16MB
__device__ float g_h[2 * 2 * Bb * Hh];    // [parity][dir][b*H]
__device__ float g_c[2 * Bb * Hh];        // [dir][b*H]

// -------- embedding: x0[s][b][e] = embed_w[input[b][s]][e] --------
__global__ void embed_kernel(const int* __restrict__ idx,
                             const float* __restrict__ ew) {
    int sb = blockIdx.x;           // 0..2047
    int s = sb >> 4, b = sb & 15;
    int token = idx[b * Ss + s];
    const float4* src = (const float4*)(ew + (size_t)token * Ee);
    float4* dst = (float4*)(g_x0 + ((size_t)s * Bb + b) * Ee);
    dst[threadIdx.x] = src[threadIdx.x];   // 128 threads x float4 = 512
}

// -------- zero h(parity 0) and c --------
__global__ void zero_state() {
    int i = blockIdx.x * 256 + threadIdx.x;
    if (i < 2 * Bb * Hh) {
        g_h[i] = 0.f;   // parity-0 slab for both dirs
        g_c[i] = 0.f;
    }
}

// ============================================================
// TF32 tensor-core GEMM  (NT: A[M][K] row-major, B[N][K] -> C=A.B^T)
// BM=BN=128, BK=32, 256 threads = 8 warps, warp tile 64x32.
// mma.sync.aligned.m16n8k8.row.col.f32.tf32.tf32.f32
// 2-stage cp.async pipeline, dynamic smem.
// mode 0: C[m*N+n] = acc + b1[n] + b2[n]
// mode 1: out[((m&15)*V + n)*S + (m>>4)] = acc + b1[n]   (vocab scatter)
// ============================================================
#define BKP 36                     // BK(32) + 4 pad (keeps 16B align, kills conflicts)
#define TILE_F (128 * BKP)         // floats per tile per stage = 4608
#define SMEM_FLOATS (4 * TILE_F)   // A(2 stages) + B(2 stages) = 18432 floats = 72KB

__device__ __forceinline__ uint32_t f2tf32(float f) {
    uint32_t r;
    asm("cvt.rna.tf32.f32 %0, %1;" : "=r"(r) : "f"(f));
    return r;
}

__device__ __forceinline__ void mma_tf32(float* c, const uint32_t* a, const uint32_t* b) {
    asm volatile(
        "mma.sync.aligned.m16n8k8.row.col.f32.tf32.tf32.f32 "
        "{%0,%1,%2,%3}, {%4,%5,%6,%7}, {%8,%9}, {%0,%1,%2,%3};"
        : "+f"(c[0]), "+f"(c[1]), "+f"(c[2]), "+f"(c[3])
        : "r"(a[0]), "r"(a[1]), "r"(a[2]), "r"(a[3]), "r"(b[0]), "r"(b[1]));
}

__device__ __forceinline__ void cp_async16(uint32_t smem_addr, const void* gptr) {
    asm volatile("cp.async.cg.shared.global [%0], [%1], 16;"
                 :: "r"(smem_addr), "l"(gptr));
}

__global__ __launch_bounds__(256)
void tf32_gemm(const float* __restrict__ A, const float* __restrict__ Bw,
               const float* __restrict__ b1, const float* __restrict__ b2,
               float* __restrict__ C, int M, int N, int K, int mode) {
    extern __shared__ float smem[];   // [A stage0][A stage1][B stage0][B stage1]
    const int tid = threadIdx.x;
    const int lane = tid & 31, wid = tid >> 5;
    const int gid = lane >> 2, tig = lane & 3;
    const int wm = (wid & 1) * 64;        // warp m offset within block
    const int wn = (wid >> 1) * 32;       // warp n offset within block
    const int bm = blockIdx.x * 128, bn = blockIdx.y * 128;

    uint32_t s_base = (uint32_t)__cvta_generic_to_shared(smem);

    float acc[4][4][4];
    #pragma unroll
    for (int i = 0; i < 4; i++)
        #pragma unroll
        for (int j = 0; j < 4; j++)
            #pragma unroll
            for (int e = 0; e < 4; e++) acc[i][j][e] = 0.f;

    const int NT = K >> 5;   // K / 32

    // per-thread gmem/smem copy assignment: 4 float4 for A, 4 for B
    // f = tid + i*256 : row = f>>3 (0..127), c4 = f&7 (float4 col)
    auto load_tiles = [&](int st, int kof) {
        #pragma unroll
        for (int i = 0; i < 4; i++) {
            int f = tid + i * 256;
            int row = f >> 3, c4 = f & 7;
            const float* srcA = A + (size_t)(bm + row) * K + kof + c4 * 4;
            uint32_t dstA = s_base + (uint32_t)(((st * 128 + row) * BKP + c4 * 4) * 4);
            cp_async16(dstA, srcA);
            const float* srcB = Bw + (size_t)(bn + row) * K + kof + c4 * 4;
            uint32_t dstB = s_base + (uint32_t)((2 * TILE_F + (st * 128 + row) * BKP + c4 * 4) * 4);
            cp_async16(dstB, srcB);
        }
        asm volatile("cp.async.commit_group;");
    };

    load_tiles(0, 0);

    for (int kt = 0; kt < NT; kt++) {
        if (kt + 1 < NT) {
            load_tiles((kt + 1) & 1, (kt + 1) * 32);
            asm volatile("cp.async.wait_group 1;");
        } else {
            asm volatile("cp.async.wait_group 0;");
        }
        __syncthreads();

        const float* as = smem + (kt & 1) * TILE_F;
        const float* bs = smem + 2 * TILE_F + (kt & 1) * TILE_F;

        #pragma unroll
        for (int ks = 0; ks < 4; ks++) {
            const int k0 = ks * 8;
            uint32_t af[4][4], bf[4][2];
            #pragma unroll
            for (int mt = 0; mt < 4; mt++) {
                int r = wm + mt * 16 + gid;
                af[mt][0] = f2tf32(as[r * BKP + k0 + tig]);
                af[mt][1] = f2tf32(as[(r + 8) * BKP + k0 + tig]);
                af[mt][2] = f2tf32(as[r * BKP + k0 + tig + 4]);
                af[mt][3] = f2tf32(as[(r + 8) * BKP + k0 + tig + 4]);
            }
            #pragma unroll
            for (int nt = 0; nt < 4; nt++) {
                int rn = wn + nt * 8 + gid;
                bf[nt][0] = f2tf32(bs[rn * BKP + k0 + tig]);
                bf[nt][1] = f2tf32(bs[rn * BKP + k0 + tig + 4]);
            }
            #pragma unroll
            for (int mt = 0; mt < 4; mt++)
                #pragma unroll
                for (int nt = 0; nt < 4; nt++)
                    mma_tf32(acc[mt][nt], af[mt], bf[nt]);
        }
        __syncthreads();
    }

    // -------- epilogue --------
    #pragma unroll
    for (int mt = 0; mt < 4; mt++) {
        int m0 = bm + wm + mt * 16 + gid;   // rows m0 and m0+8
        #pragma unroll
        for (int nt = 0; nt < 4; nt++) {
            int n = bn + wn + nt * 8 + tig * 2;   // cols n, n+1
            float* a = acc[mt][nt];
            if (mode == 0) {
                float bb0 = b1[n] + b2[n];
                float bb1 = b1[n + 1] + b2[n + 1];
                *(float2*)(C + (size_t)m0 * N + n) = make_float2(a[0] + bb0, a[1] + bb1);
                *(float2*)(C + (size_t)(m0 + 8) * N + n) = make_float2(a[2] + bb0, a[3] + bb1);
            } else {
                float bb0 = b1[n], bb1 = b1[n + 1];
                int s0 = m0 >> 4, b0 = m0 & 15;
                int s1 = (m0 + 8) >> 4, b1i = (m0 + 8) & 15;
                C[((size_t)b0 * Vv + n) * Ss + s0]       = a[0] + bb0;
                C[((size_t)b0 * Vv + n + 1) * Ss + s0]   = a[1] + bb1;
                C[((size_t)b1i * Vv + n) * Ss + s1]      = a[2] + bb0;
                C[((size_t)b1i * Vv + n + 1) * Ss + s1]  = a[3] + bb1;
            }
        }
    }
}

// -------- fused LSTM step: both directions, one time step --------
__global__ __launch_bounds__(128)
void lstm_step(const float* __restrict__ xg_f, const float* __restrict__ xg_b,
               const float* __restrict__ Whh_f, const float* __restrict__ Whh_b,
               float* __restrict__ xnext, int t) {
    __shared__ float hs[Hh * 17];   // hs[k*17 + b], padded, conflict-free both ways

    int dir = blockIdx.x & 1;
    int jblk = blockIdx.x >> 1;         // 0..63
    int tid = threadIdx.x;
    int b = tid & 15, jl = tid >> 4;    // jl 0..7
    int j = jblk * 8 + jl;

    const float* Whh = dir ? Whh_b : Whh_f;
    const float* xg = dir ? xg_b : xg_f;
    int tt = dir ? (Ss - 1 - t) : t;

    const float* hread = g_h + (size_t)(t & 1) * (2 * Bb * Hh) + (size_t)dir * (Bb * Hh);
    float* hwrite = g_h + (size_t)((t + 1) & 1) * (2 * Bb * Hh) + (size_t)dir * (Bb * Hh);
    float* cstate = g_c + (size_t)dir * (Bb * Hh);

    for (int idx = tid; idx < Bb * Hh; idx += 128) {
        int bb = idx >> 9;
        int kk = idx & 511;
        hs[kk * 17 + bb] = hread[idx];
    }
    __syncthreads();

    const float4* wi = (const float4*)(Whh + (size_t)(0 * Hh + j) * Hh);
    const float4* wf = (const float4*)(Whh + (size_t)(1 * Hh + j) * Hh);
    const float4* wg = (const float4*)(Whh + (size_t)(2 * Hh + j) * Hh);
    const float4* wo = (const float4*)(Whh + (size_t)(3 * Hh + j) * Hh);

    float ai = 0.f, af = 0.f, ag = 0.f, ao = 0.f;
    #pragma unroll 4
    for (int k4 = 0; k4 < Hh / 4; k4++) {
        float4 vi = __ldg(wi + k4);
        float4 vf = __ldg(wf + k4);
        float4 vg = __ldg(wg + k4);
        float4 vo = __ldg(wo + k4);
        int k = k4 * 4;
        float h0 = hs[(k + 0) * 17 + b];
        float h1 = hs[(k + 1) * 17 + b];
        float h2 = hs[(k + 2) * 17 + b];
        float h3 = hs[(k + 3) * 17 + b];
        ai += vi.x * h0 + vi.y * h1 + vi.z * h2 + vi.w * h3;
        af += vf.x * h0 + vf.y * h1 + vf.z * h2 + vf.w * h3;
        ag += vg.x * h0 + vg.y * h1 + vg.z * h2 + vg.w * h3;
        ao += vo.x * h0 + vo.y * h1 + vo.z * h2 + vo.w * h3;
    }

    size_t base = ((size_t)tt * Bb + b) * (size_t)H4;
    ai += xg[base + 0 * Hh + j];
    af += xg[base + 1 * Hh + j];
    ag += xg[base + 2 * Hh + j];
    ao += xg[base + 3 * Hh + j];

    float ii = 1.f / (1.f + __expf(-ai));
    float ff = 1.f / (1.f + __expf(-af));
    float gg = tanhf(ag);
    float oo = 1.f / (1.f + __expf(-ao));

    int sidx = b * Hh + j;
    float c = ff * cstate[sidx] + ii * gg;
    float h = oo * tanhf(c);
    cstate[sidx] = c;
    hwrite[sidx] = h;
    xnext[((size_t)tt * Bb + b) * (size_t)(2 * Hh) + (size_t)dir * Hh + j] = h;
}

// ---------------- host launcher ----------------
extern "C" void kernel_launch(void* const* d_in, const int* in_sizes, int n_in,
                              void* d_out, int out_size) {
    const int* input = (const int*)d_in[0];
    const float* embed_w = (const float*)d_in[1];
    const float* Wih[2][2]; const float* Whh[2][2];
    const float* bih[2][2]; const float* bhh[2][2];
    int p = 2;
    for (int l = 0; l < 2; l++) {
        for (int d = 0; d < 2; d++) {  // d=0 fwd, d=1 bwd
            Wih[l][d] = (const float*)d_in[p++];
            Whh[l][d] = (const float*)d_in[p++];
            bih[l][d] = (const float*)d_in[p++];
            bhh[l][d] = (const float*)d_in[p++];
        }
    }
    const float* lin_w = (const float*)d_in[18];
    const float* lin_b = (const float*)d_in[19];
    float* out = (float*)d_out;

    float *x0p, *x1p, *x2p, *xgf, *xgb;
    cudaGetSymbolAddress((void**)&x0p, g_x0);
    cudaGetSymbolAddress((void**)&x1p, g_x1);
    cudaGetSymbolAddress((void**)&x2p, g_x2);
    cudaGetSymbolAddress((void**)&xgf, g_xg_f);
    cudaGetSymbolAddress((void**)&xgb, g_xg_b);

    static int smem_set = 0;
    if (!smem_set) {
        cudaFuncSetAttribute(tf32_gemm, cudaFuncAttributeMaxDynamicSharedMemorySize,
                             SMEM_FLOATS * 4);
        smem_set = 1;
    }
    const size_t smem_bytes = SMEM_FLOATS * 4;

    // 1) embedding
    embed_kernel<<<MROWS, 128>>>(input, embed_w);

    const float* xin = x0p;
    float* xouts[2] = {x1p, x2p};
    int kdims[2] = {Ee, 2 * Hh};

    for (int l = 0; l < 2; l++) {
        int K = kdims[l];
        dim3 ggrid(MROWS / 128, H4 / 128);   // x = m-tiles, y = n-tiles
        tf32_gemm<<<ggrid, 256, smem_bytes>>>(xin, Wih[l][0], bih[l][0], bhh[l][0],
                                              xgf, MROWS, H4, K, 0);
        tf32_gemm<<<ggrid, 256, smem_bytes>>>(xin, Wih[l][1], bih[l][1], bhh[l][1],
                                              xgb, MROWS, H4, K, 0);
        zero_state<<<64, 256>>>();
        for (int t = 0; t < Ss; t++) {
            lstm_step<<<128, 128>>>(xgf, xgb, Whh[l][0], Whh[l][1], xouts[l], t);
        }
        xin = xouts[l];
    }

    // 3) vocab projection with [B,V,S] scatter
    // x = m-tiles (16) fastest -> co-resident CTAs share lin_w tiles via L2
    dim3 ogrid(MROWS / 128, Vv / 128);
    tf32_gemm<<<ogrid, 256, smem_bytes>>>(x2p, lin_w, lin_b, nullptr,
                                          out, MROWS, Vv, 2 * Hh, 1);
}